// round 5
// baseline (speedup 1.0000x reference)
#include <cuda_runtime.h>

// Problem constants (fixed instance: B=32, T=512, C=6625, L=32)
#define BB 32
#define TT 512
#define CC 6625
#define LL 32
#define SS 65        // 2L+1 extended states
#define RSP 33       // row stride: [0..31]=label lin emissions, [32]=blank lin
#define BLANK_ID 6624
#define LOG2E 1.4426950408889634f
#define LN2d  0.6931471805599453
#define CSHIFT 10.0f     // constant log2 boost per emission (exactly representable)
#define RN_TARGET 50     // renorm target exponent: keep warp max near 2^50
#define NDS 255          // number of composed double steps (t = 2..511)

// Static device scratch (no runtime allocation)
__device__ float g_emit[(size_t)BB * TT * RSP];   // linear-domain boosted emissions
__device__ float g_partial[BB];
__device__ int   g_done = 0;                      // cross-block completion counter

__device__ __forceinline__ float ex2f_(float x) {
    float y; asm("ex2.approx.ftz.f32 %0, %1;" : "=f"(y) : "f"(x)); return y;
}
__device__ __forceinline__ float lg2f_(float x) {
    float y; asm("lg2.approx.ftz.f32 %0, %1;" : "=f"(y) : "f"(x)); return y;
}

// ---------------------------------------------------------------------------
// Kernel 1: per-(batch, class) column gather + time-axis logsumexp + direct
// linearization. Grid (33, BB): s<32 -> label s, s==32 -> blank.
// Writes emit_lin = 2^(lv + CSHIFT), lv = log2-normalized emission.
// ---------------------------------------------------------------------------
__global__ void gather_lse_kernel(const float* __restrict__ lp,
                                  const int* __restrict__ targets) {
    const int s   = blockIdx.x;   // 0..32
    const int b   = blockIdx.y;
    const int tid = threadIdx.x;  // 0..127

    const int c = (s < 32) ? targets[b * LL + s] : BLANK_ID;
    const float* col = lp + (size_t)b * TT * CC + c;

    float v[4];
#pragma unroll
    for (int k = 0; k < 4; ++k)
        v[k] = __ldcs(col + (size_t)(tid + k * 128) * CC);

    // block max
    float m = fmaxf(fmaxf(v[0], v[1]), fmaxf(v[2], v[3]));
#pragma unroll
    for (int o = 16; o; o >>= 1) m = fmaxf(m, __shfl_xor_sync(0xffffffffu, m, o));
    __shared__ float redm[4];
    const int w = tid >> 5;
    if ((tid & 31) == 0) redm[w] = m;
    __syncthreads();
    m = fmaxf(fmaxf(redm[0], redm[1]), fmaxf(redm[2], redm[3]));

    // block sum of 2^((v-m)*log2e)
    float sum = 0.f;
#pragma unroll
    for (int k = 0; k < 4; ++k) sum += ex2f_((v[k] - m) * LOG2E);
#pragma unroll
    for (int o = 16; o; o >>= 1) sum += __shfl_xor_sync(0xffffffffu, sum, o);
    __shared__ float reds[4];
    if ((tid & 31) == 0) reds[w] = sum;
    __syncthreads();
    sum = reds[0] + reds[1] + reds[2] + reds[3];

    const float lse2 = m * LOG2E + lg2f_(sum);   // log2-domain logsumexp over t

    float* dst = g_emit + (size_t)b * TT * RSP + s;
#pragma unroll
    for (int k = 0; k < 4; ++k)
        dst[(size_t)(tid + k * 128) * RSP] =
            ex2f_(v[k] * LOG2E - lse2 + CSHIFT);
}

// ---------------------------------------------------------------------------
// Kernel 2: CTC alpha recursion, TWO time steps per shuffle.
// One warp per batch. Lane i owns states 2i (aE), 2i+1 (aO); lane 31 also
// owns state 64 (aX). Composed double step (t, t+1):
//   u = aE + pO            (= E(t)/b_t)
//   v = aO + aE + za*pO    (= O(t)/l_t)
//   w = pO + pE + pza*qO   (= neighbor O(t)/l_{i-1,t})
//   E' = (u*b_t + w*lm_zb) * b_{t+1}
//   O' = (u*b_t + v*l_t + w*lm_za) * l_{t+1}
//   X' = ((aX+aO)*b_t + v*l_t) * b_{t+1}
// where lm_* are the neighbor-label emissions premultiplied by lane masks.
// Renorm every 16 t to 2^RN_TARGET (exact power-of-2, exponent tracked).
// ---------------------------------------------------------------------------
__global__ void ctc_kernel(const int* __restrict__ targets,
                           const int* __restrict__ ilens,
                           const int* __restrict__ tlens,
                           float* __restrict__ out) {
    const int b    = blockIdx.x;
    const int lane = threadIdx.x;
    const float* em = g_emit + (size_t)b * TT * RSP;

    const int tgt = targets[b * LL + lane];
    const int tm1 = (lane > 0) ? targets[b * LL + lane - 1] : BLANK_ID;
    const int tm2 = (lane > 1) ? targets[b * LL + lane - 2] : BLANK_ID;
    const float za  = (lane > 0 && tgt != BLANK_ID && tgt != tm1) ? 1.f : 0.f;
    const float pza = (lane > 1 && tm1 != BLANK_ID && tm1 != tm2) ? 1.f : 0.f;
    const float zb  = (lane > 0) ? 1.f : 0.f;
    int ilen = ilens[b];
    if (ilen > TT) ilen = TT;

    // t = 0 init
    float aE = (lane == 0) ? em[32] : 0.f;
    float aO = (lane == 0) ? em[0]  : 0.f;
    float aX = 0.f;
    int   SH = 0;

    // t = 1 single step
    {
        const float l1v = em[RSP + lane];
        const float b1v = em[RSP + 32];
        float pO = __shfl_up_sync(0xffffffffu, aO, 1);
        const float u = fmaf(pO, zb, aE);
        const float v = fmaf(pO, za, aO + aE);
        const float nE = u * b1v, nO = v * l1v, nX = (aX + aO) * b1v;
        if (1 < ilen) { aE = nE; aO = nO; aX = nX; }
    }

    // prefetch 5 double-steps (t = 2..11)
    float L0[5], L1[5], LMB[5], LMA[5], B0[5], B1[5];
#pragma unroll
    for (int k = 0; k < 5; ++k) {
        const int t = 2 + 2 * k;
        L0[k] = em[(size_t)t * RSP + lane];
        L1[k] = em[(size_t)(t + 1) * RSP + lane];
        const float lm = em[(size_t)t * RSP + lane - 1];  // lane0: harmless read
        LMB[k] = lm * zb; LMA[k] = lm * za;
        B0[k] = em[(size_t)t * RSP + 32];
        B1[k] = em[(size_t)(t + 1) * RSP + 32];
    }

    const bool full = (ilen == TT);   // warp-uniform specialization

    if (full) {
#pragma unroll 5
        for (int ds = 0; ds < NDS; ++ds) {
            const int sl = ds % 5;
            const float lt = L0[sl], lt1 = L1[sl];
            const float lmzb = LMB[sl], lmza = LMA[sl];
            const float bt = B0[sl], bt1 = B1[sl];

            float pO = __shfl_up_sync(0xffffffffu, aO, 1);
            float pE = __shfl_up_sync(0xffffffffu, aE, 1);
            float qO = __shfl_up_sync(0xffffffffu, aO, 2);
            const float s0 = aO + aE;      // pre-shfl, overlaps latency
            const float x0 = aX + aO;

            const float u = fmaf(pO, zb, aE);
            const float v = fmaf(pO, za, s0);
            const float w = fmaf(qO, pza, pO + pE);
            const float ub = u * bt;
            const float vl = v * lt;
            const float x1 = x0 * bt;

            aE = fmaf(w, lmzb, ub) * bt1;
            aO = fmaf(w, lmza, ub + vl) * lt1;
            aX = fmaf(v, lt, x1) * bt1;

            if (((ds + 1) & 7) == 0) {   // every 16 t: exact pow2 renorm
                float m = fmaxf(fmaxf(aE, aO), aX);
#pragma unroll
                for (int o = 16; o; o >>= 1)
                    m = fmaxf(m, __shfl_xor_sync(0xffffffffu, m, o));
                if (m > 0.f) {
                    const int e = ((__float_as_int(m) >> 23) & 255) - 127;
                    int sh = RN_TARGET - e;
                    if (sh > 127)  sh = 127;
                    if (sh < -126) sh = -126;
                    const float sc = __int_as_float((127 + sh) << 23);
                    aE *= sc; aO *= sc; aX *= sc;
                    SH += sh;
                }
            }

            const int pf = ds + 5;
            if (pf < NDS) {
                const int t = 2 + 2 * pf;
                L0[sl] = em[(size_t)t * RSP + lane];
                L1[sl] = em[(size_t)(t + 1) * RSP + lane];
                const float lm = em[(size_t)t * RSP + lane - 1];
                LMB[sl] = lm * zb; LMA[sl] = lm * za;
                B0[sl] = em[(size_t)t * RSP + 32];
                B1[sl] = em[(size_t)(t + 1) * RSP + 32];
            }
        }
    } else {
#pragma unroll 5
        for (int ds = 0; ds < NDS; ++ds) {
            const int sl = ds % 5;
            const int t = 2 + 2 * ds;
            const float lt = L0[sl], lt1 = L1[sl];
            const float lmzb = LMB[sl], lmza = LMA[sl];
            const float bt = B0[sl], bt1 = B1[sl];

            float pO = __shfl_up_sync(0xffffffffu, aO, 1);
            float pE = __shfl_up_sync(0xffffffffu, aE, 1);
            float qO = __shfl_up_sync(0xffffffffu, aO, 2);
            const float s0 = aO + aE;
            const float x0 = aX + aO;

            const float u = fmaf(pO, zb, aE);
            const float v = fmaf(pO, za, s0);
            const float w = fmaf(qO, pza, pO + pE);
            const float ub = u * bt;     // single-step E(t)
            const float vl = v * lt;     // single-step O(t)
            const float x1 = x0 * bt;    // single-step X(t)

            const float e2 = fmaf(w, lmzb, ub) * bt1;
            const float o2 = fmaf(w, lmza, ub + vl) * lt1;
            const float x2 = fmaf(v, lt, x1) * bt1;

            const bool p1 = (t < ilen), p2 = (t + 1 < ilen);
            aE = p2 ? e2 : (p1 ? ub : aE);
            aO = p2 ? o2 : (p1 ? vl : aO);
            aX = p2 ? x2 : (p1 ? x1 : aX);

            if (((ds + 1) & 7) == 0) {
                float m = fmaxf(fmaxf(aE, aO), aX);
#pragma unroll
                for (int o = 16; o; o >>= 1)
                    m = fmaxf(m, __shfl_xor_sync(0xffffffffu, m, o));
                if (m > 0.f) {
                    const int e = ((__float_as_int(m) >> 23) & 255) - 127;
                    int sh = RN_TARGET - e;
                    if (sh > 127)  sh = 127;
                    if (sh < -126) sh = -126;
                    const float sc = __int_as_float((127 + sh) << 23);
                    aE *= sc; aO *= sc; aX *= sc;
                    SH += sh;
                }
            }

            const int pf = ds + 5;
            if (pf < NDS) {
                const int tp = 2 + 2 * pf;
                L0[sl] = em[(size_t)tp * RSP + lane];
                L1[sl] = em[(size_t)(tp + 1) * RSP + lane];
                const float lm = em[(size_t)tp * RSP + lane - 1];
                LMB[sl] = lm * zb; LMA[sl] = lm * za;
                B0[sl] = em[(size_t)tp * RSP + 32];
                B1[sl] = em[(size_t)(tp + 1) * RSP + 32];
            }
        }
    }

    __shared__ float fin[SS];
    fin[2 * lane]     = aE;
    fin[2 * lane + 1] = aO;
    if (lane == 31) fin[64] = aX;
    __syncwarp();

    if (lane == 0) {
        const int tl = tlens[b];
        const int i1 = 2 * tl;
        const int i2 = (2 * tl - 1 > 0) ? (2 * tl - 1) : 0;
        const float tot = fin[i1] + fin[i2];
        float loss;
        if (tot > 0.f) {
            // stored = true * 2^(CSHIFT*ilen + SH)
            const double ll2 = (double)lg2f_(tot)
                             - (double)SH - (double)CSHIFT * (double)ilen;
            loss = (float)(-LN2d * ll2);
            if (!(loss < 1e20f)) loss = 0.f;   // zero_infinity
        } else {
            loss = 0.f;                        // zero total prob -> inf -> 0
        }
        const int dn = (tl > 1) ? tl : 1;
        g_partial[b] = loss / (float)dn;
        __threadfence();
    }
    __syncwarp();

    // deterministic last-block batch mean (fixed-tree reduction, counter reset)
    int old = 0;
    if (lane == 0) old = atomicAdd(&g_done, 1);
    old = __shfl_sync(0xffffffffu, old, 0);
    if (old == BB - 1) {
        float v = *((volatile float*)&g_partial[lane]);
#pragma unroll
        for (int o = 16; o; o >>= 1) v += __shfl_xor_sync(0xffffffffu, v, o);
        if (lane == 0) {
            out[0] = v * (1.0f / (float)BB);
            g_done = 0;                        // reset for next graph replay
        }
    }
}

extern "C" void kernel_launch(void* const* d_in, const int* in_sizes, int n_in,
                              void* d_out, int out_size) {
    const float* lp      = (const float*)d_in[0];
    const int*   targets = (const int*)d_in[1];
    const int*   ilens   = (const int*)d_in[2];
    const int*   tlens   = (const int*)d_in[3];
    (void)in_sizes; (void)n_in; (void)out_size;

    gather_lse_kernel<<<dim3(RSP, BB), 128>>>(lp, targets);
    ctc_kernel<<<BB, 32>>>(targets, ilens, tlens, (float*)d_out);
}

// round 6
// speedup vs baseline: 2.0661x; 2.0661x over previous
#include <cuda_runtime.h>

// Problem constants (fixed instance: B=32, T=512, C=6625, L=32)
#define BB 32
#define TT 512
#define TH 256       // meet-in-the-middle point
#define CC 6625
#define LL 32
#define SS 65        // 2L+1 extended states
#define NSC 33       // stored emission rows per batch: 32 labels + blank
#define BLANK_ID 6624
#define LOG2E 1.4426950408889634f
#define LN2d  0.6931471805599453
#define CSHIFT 10.0f     // constant log2 boost per emission
#define RN_TARGET 40     // renorm target exponent

// Static device scratch (no runtime allocation). [b][s][t] layout, s-major.
__device__ __align__(128) float g_emit[(size_t)BB * NSC * TT];
__device__ float g_partial[BB];
__device__ int   g_done = 0;

__device__ __forceinline__ float ex2f_(float x) {
    float y; asm("ex2.approx.ftz.f32 %0, %1;" : "=f"(y) : "f"(x)); return y;
}
__device__ __forceinline__ float lg2f_(float x) {
    float y; asm("lg2.approx.ftz.f32 %0, %1;" : "=f"(y) : "f"(x)); return y;
}

// ---------------------------------------------------------------------------
// Kernel 1: per-(batch, class) column gather + time-axis logsumexp + direct
// linearization. Grid (33, BB): s<32 -> label s, s==32 -> blank.
// Writes emit_lin = 2^(lv + CSHIFT) into g_emit[b][s][t] (coalesced in t).
// ---------------------------------------------------------------------------
__global__ void gather_lse_kernel(const float* __restrict__ lp,
                                  const int* __restrict__ targets) {
    const int s   = blockIdx.x;   // 0..32
    const int b   = blockIdx.y;
    const int tid = threadIdx.x;  // 0..127

    const int c = (s < 32) ? targets[b * LL + s] : BLANK_ID;
    const float* col = lp + (size_t)b * TT * CC + c;

    float v[4];
#pragma unroll
    for (int k = 0; k < 4; ++k)
        v[k] = __ldcs(col + (size_t)(tid + k * 128) * CC);

    // block max
    float m = fmaxf(fmaxf(v[0], v[1]), fmaxf(v[2], v[3]));
#pragma unroll
    for (int o = 16; o; o >>= 1) m = fmaxf(m, __shfl_xor_sync(0xffffffffu, m, o));
    __shared__ float redm[4];
    const int w = tid >> 5;
    if ((tid & 31) == 0) redm[w] = m;
    __syncthreads();
    m = fmaxf(fmaxf(redm[0], redm[1]), fmaxf(redm[2], redm[3]));

    // block sum of 2^((v-m)*log2e)
    float sum = 0.f;
#pragma unroll
    for (int k = 0; k < 4; ++k) sum += ex2f_((v[k] - m) * LOG2E);
#pragma unroll
    for (int o = 16; o; o >>= 1) sum += __shfl_xor_sync(0xffffffffu, sum, o);
    __shared__ float reds[4];
    if ((tid & 31) == 0) reds[w] = sum;
    __syncthreads();
    sum = reds[0] + reds[1] + reds[2] + reds[3];

    const float lse2 = m * LOG2E + lg2f_(sum);   // log2 logsumexp over t

    float* dst = g_emit + ((size_t)b * NSC + s) * TT;
#pragma unroll
    for (int k = 0; k < 4; ++k)
        dst[tid + k * 128] = ex2f_(v[k] * LOG2E - lse2 + CSHIFT);
}

// --- per-step macros -------------------------------------------------------
#define FSTEP(el, eb) do {                                          \
    float pO_ = __shfl_up_sync(0xffffffffu, aO, 1);                 \
    float s0_ = aO + aE;                                            \
    float x0_ = aX + aO;                                            \
    float u_  = fmaf(pO_, zb, aE);                                  \
    float v_  = fmaf(pO_, za, s0_);                                 \
    aE = u_ * (eb); aO = v_ * (el); aX = x0_ * (eb);                \
} while (0)

#define FSTEPP(el, eb, tcur) do {                                   \
    float pO_ = __shfl_up_sync(0xffffffffu, aO, 1);                 \
    float s0_ = aO + aE;                                            \
    float x0_ = aX + aO;                                            \
    float u_  = fmaf(pO_, zb, aE);                                  \
    float v_  = fmaf(pO_, za, s0_);                                 \
    float nE_ = u_ * (eb), nO_ = v_ * (el), nX_ = x0_ * (eb);       \
    if ((tcur) < ilen) { aE = nE_; aO = nO_; aX = nX_; }            \
} while (0)

#define BSTEP(el, eb) do {                                          \
    float t1_ = (el) * bO;                                          \
    float t2_ = (eb) * bE;                                          \
    float d_  = fmaf(t1_, za, t2_);                                 \
    float pd_ = __shfl_down_sync(0xffffffffu, d_, 1);               \
    float xb_ = (eb) * bX;                                          \
    if (lane == 31) pd_ = xb_;                                      \
    bE = t2_ + t1_; bO = t1_ + pd_; bX = xb_;                       \
} while (0)

#define BSTEPP(el, eb, ecur) do {                                   \
    float t1_ = (el) * bO;                                          \
    float t2_ = (eb) * bE;                                          \
    float d_  = fmaf(t1_, za, t2_);                                 \
    float pd_ = __shfl_down_sync(0xffffffffu, d_, 1);               \
    float xb_ = (eb) * bX;                                          \
    if (lane == 31) pd_ = xb_;                                      \
    float nE_ = t2_ + t1_, nO_ = t1_ + pd_;                         \
    if ((ecur) < ilen) { bE = nE_; bO = nO_; bX = xb_; }            \
} while (0)

#define RENORM(r0, r1, r2, SH) do {                                 \
    float m_ = fmaxf(fmaxf(r0, r1), r2);                            \
    _Pragma("unroll")                                               \
    for (int o_ = 16; o_; o_ >>= 1)                                 \
        m_ = fmaxf(m_, __shfl_xor_sync(0xffffffffu, m_, o_));       \
    if (m_ > 0.f) {                                                 \
        const int e_ = ((__float_as_int(m_) >> 23) & 255) - 127;    \
        int sh_ = RN_TARGET - e_;                                   \
        if (sh_ > 127)  sh_ = 127;                                  \
        if (sh_ < -126) sh_ = -126;                                 \
        const float sc_ = __int_as_float((127 + sh_) << 23);        \
        r0 *= sc_; r1 *= sc_; r2 *= sc_;                            \
        SH += sh_;                                                  \
    }                                                               \
} while (0)

// ---------------------------------------------------------------------------
// Kernel 2: meet-in-the-middle CTC. One block (64 threads) per batch.
// Warp 0: forward alpha over t=0..TH-1. Warp 1: backward beta over
// t=TT-2..TH-1 (consuming emissions TT-1..TH). Combine at t=TH-1 via
// dot(alpha, beta). Linear domain, periodic exact pow2 renorm.
// ---------------------------------------------------------------------------
__global__ void ctc_kernel(const int* __restrict__ targets,
                           const int* __restrict__ ilens,
                           const int* __restrict__ tlens,
                           float* __restrict__ out) {
    const int b    = blockIdx.x;
    const int tid  = threadIdx.x;
    const int wid  = tid >> 5;
    const int lane = tid & 31;
    const float* em = g_emit + (size_t)b * NSC * TT;

    const int tgt = targets[b * LL + lane];
    const int tm1 = (lane > 0) ? targets[b * LL + lane - 1] : BLANK_ID;
    const float za = (lane > 0 && tgt != BLANK_ID && tgt != tm1) ? 1.f : 0.f;
    const float zb = (lane > 0) ? 1.f : 0.f;
    int ilen = ilens[b];
    if (ilen > TT) ilen = TT;

    __shared__ float fA[SS], fB[SS];
    __shared__ int   sSH[2];

    const float* pL = em + (size_t)lane * TT;   // this lane's label emissions
    const float* pB = em + (size_t)32  * TT;    // blank emissions (broadcast)

    if (wid == 0) {
        // ----- forward: alpha, t = 0 .. TH-1 -----
        float aE = (lane == 0) ? 1.f : 0.f;     // virtual alpha_{-1}
        float aO = 0.f, aX = 0.f;
        int SH = 0;

        float4 La = *(const float4*)(pL + 0), Ba = *(const float4*)(pB + 0);
        float4 Lb = *(const float4*)(pL + 4), Bb = *(const float4*)(pB + 4);

#pragma unroll 1
        for (int g2 = 0; g2 < 32; ++g2) {
            const int t0 = 8 * g2;
            // group A: t = t0..t0+3
            if (t0 + 3 < ilen) {
                FSTEP(La.x, Ba.x); FSTEP(La.y, Ba.y);
                FSTEP(La.z, Ba.z); FSTEP(La.w, Ba.w);
            } else {
                FSTEPP(La.x, Ba.x, t0 + 0); FSTEPP(La.y, Ba.y, t0 + 1);
                FSTEPP(La.z, Ba.z, t0 + 2); FSTEPP(La.w, Ba.w, t0 + 3);
            }
            if (t0 + 8 < TH) {
                La = *(const float4*)(pL + t0 + 8);
                Ba = *(const float4*)(pB + t0 + 8);
            }
            // group B: t = t0+4..t0+7
            if (t0 + 7 < ilen) {
                FSTEP(Lb.x, Bb.x); FSTEP(Lb.y, Bb.y);
                FSTEP(Lb.z, Bb.z); FSTEP(Lb.w, Bb.w);
            } else {
                FSTEPP(Lb.x, Bb.x, t0 + 4); FSTEPP(Lb.y, Bb.y, t0 + 5);
                FSTEPP(Lb.z, Bb.z, t0 + 6); FSTEPP(Lb.w, Bb.w, t0 + 7);
            }
            if (t0 + 12 < TH) {
                Lb = *(const float4*)(pL + t0 + 12);
                Bb = *(const float4*)(pB + t0 + 12);
            }
            RENORM(aE, aO, aX, SH);   // every 8 steps
        }

        fA[2 * lane] = aE;
        fA[2 * lane + 1] = aO;
        if (lane == 31) fA[64] = aX;
        if (lane == 0)  sSH[0] = SH;
    } else {
        // ----- backward: beta, consuming emissions e = TT-1 down to TH -----
        const int tl = tlens[b];
        const int i1 = 2 * tl;
        const int i2 = (2 * tl - 1 > 0) ? (2 * tl - 1) : 0;
        float bE = ((2 * lane == i1) || (2 * lane == i2)) ? 1.f : 0.f;
        float bO = (2 * lane + 1 == i2) ? 1.f : 0.f;
        float bX = (i1 == 64) ? 1.f : 0.f;   // only lane 31's copy is used
        int SH = 0;

        float4 La = *(const float4*)(pL + TT - 4), Ba = *(const float4*)(pB + TT - 4);
        float4 Lb = *(const float4*)(pL + TT - 8), Bb = *(const float4*)(pB + TT - 8);

#pragma unroll 1
        for (int g2 = 0; g2 < 32; ++g2) {
            const int ea = TT - 4 - 8 * g2;   // group A covers e = ea+3..ea
            // group A: consume descending .w .z .y .x
            if (ea + 3 < ilen) {
                BSTEP(La.w, Ba.w); BSTEP(La.z, Ba.z);
                BSTEP(La.y, Ba.y); BSTEP(La.x, Ba.x);
            } else {
                BSTEPP(La.w, Ba.w, ea + 3); BSTEPP(La.z, Ba.z, ea + 2);
                BSTEPP(La.y, Ba.y, ea + 1); BSTEPP(La.x, Ba.x, ea + 0);
            }
            if (ea - 8 >= TH) {
                La = *(const float4*)(pL + ea - 8);
                Ba = *(const float4*)(pB + ea - 8);
            }
            // group B: covers e = ea-1..ea-4
            if (ea - 1 < ilen) {
                BSTEP(Lb.w, Bb.w); BSTEP(Lb.z, Bb.z);
                BSTEP(Lb.y, Bb.y); BSTEP(Lb.x, Bb.x);
            } else {
                BSTEPP(Lb.w, Bb.w, ea - 1); BSTEPP(Lb.z, Bb.z, ea - 2);
                BSTEPP(Lb.y, Bb.y, ea - 3); BSTEPP(Lb.x, Bb.x, ea - 4);
            }
            if (ea - 12 >= TH) {
                Lb = *(const float4*)(pL + ea - 12);
                Bb = *(const float4*)(pB + ea - 12);
            }
            RENORM(bE, bO, bX, SH);   // every 8 steps
        }

        fB[2 * lane] = bE;
        fB[2 * lane + 1] = bO;
        if (lane == 31) fB[64] = bX;
        if (lane == 0)  sSH[1] = SH;
    }

    __syncthreads();

    if (wid == 0) {
        // dot(alpha_{TH-1}, beta_{TH-1})
        float prod = fA[2 * lane] * fB[2 * lane]
                   + fA[2 * lane + 1] * fB[2 * lane + 1];
        if (lane == 31) prod = fmaf(fA[64], fB[64], prod);
#pragma unroll
        for (int o = 16; o; o >>= 1) prod += __shfl_xor_sync(0xffffffffu, prod, o);

        if (lane == 0) {
            const float tot = prod;
            float loss;
            if (tot > 0.f) {
                // stored = true * 2^(CSHIFT*ilen + SHa + SHb)
                const double ll2 = (double)lg2f_(tot)
                                 - (double)(sSH[0] + sSH[1])
                                 - (double)CSHIFT * (double)ilen;
                loss = (float)(-LN2d * ll2);
                if (!(loss < 1e20f)) loss = 0.f;   // zero_infinity
            } else {
                loss = 0.f;
            }
            const int tl = tlens[b];
            const int dn = (tl > 1) ? tl : 1;
            g_partial[b] = loss / (float)dn;
            __threadfence();
        }
        __syncwarp();

        // deterministic last-block batch mean (fixed-tree, counter reset)
        int old = 0;
        if (lane == 0) old = atomicAdd(&g_done, 1);
        old = __shfl_sync(0xffffffffu, old, 0);
        if (old == BB - 1) {
            float v = *((volatile float*)&g_partial[lane]);
#pragma unroll
            for (int o = 16; o; o >>= 1) v += __shfl_xor_sync(0xffffffffu, v, o);
            if (lane == 0) {
                out[0] = v * (1.0f / (float)BB);
                g_done = 0;                        // reset for next graph replay
            }
        }
    }
}

extern "C" void kernel_launch(void* const* d_in, const int* in_sizes, int n_in,
                              void* d_out, int out_size) {
    const float* lp      = (const float*)d_in[0];
    const int*   targets = (const int*)d_in[1];
    const int*   ilens   = (const int*)d_in[2];
    const int*   tlens   = (const int*)d_in[3];
    (void)in_sizes; (void)n_in; (void)out_size;

    gather_lse_kernel<<<dim3(NSC, BB), 128>>>(lp, targets);
    ctc_kernel<<<BB, 64>>>(targets, ilens, tlens, (float*)d_out);
}

// round 7
// speedup vs baseline: 2.0809x; 1.0071x over previous
#include <cuda_runtime.h>

// Problem constants (fixed instance: B=32, T=512, C=6625, L=32)
#define BB 32
#define TT 512
#define TH 256       // meet-in-the-middle point
#define CC 6625
#define LL 32
#define SS 65        // 2L+1 extended states
#define NSC 33       // stored emission rows per batch: 32 labels + blank
#define BLANK_ID 6624
#define LOG2E 1.4426950408889634f
#define LN2d  0.6931471805599453
#define CSHIFT 10.0f     // constant log2 boost per emission
#define RN_TARGET 40     // renorm target exponent

// Static device scratch (no runtime allocation). [b][s][t] layout, s-major.
__device__ __align__(128) float g_emit[(size_t)BB * NSC * TT];
__device__ float g_partial[BB];
__device__ int   g_cnt[BB];      // per-batch gather-completion counters (zero-init)
__device__ int   g_done = 0;     // batch-mean completion counter

__device__ __forceinline__ float ex2f_(float x) {
    float y; asm("ex2.approx.ftz.f32 %0, %1;" : "=f"(y) : "f"(x)); return y;
}
__device__ __forceinline__ float lg2f_(float x) {
    float y; asm("lg2.approx.ftz.f32 %0, %1;" : "=f"(y) : "f"(x)); return y;
}
__device__ __forceinline__ float4 ldcg4_(const float* p) {
    return __ldcg((const float4*)p);
}

// --- per-step macros -------------------------------------------------------
#define FSTEP(el, eb) do {                                          \
    float pO_ = __shfl_up_sync(0xffffffffu, aO, 1);                 \
    float s0_ = aO + aE;                                            \
    float x0_ = aX + aO;                                            \
    float u_  = fmaf(pO_, zb, aE);                                  \
    float v_  = fmaf(pO_, za, s0_);                                 \
    aE = u_ * (eb); aO = v_ * (el); aX = x0_ * (eb);                \
} while (0)

#define FSTEPP(el, eb, tcur) do {                                   \
    float pO_ = __shfl_up_sync(0xffffffffu, aO, 1);                 \
    float s0_ = aO + aE;                                            \
    float x0_ = aX + aO;                                            \
    float u_  = fmaf(pO_, zb, aE);                                  \
    float v_  = fmaf(pO_, za, s0_);                                 \
    float nE_ = u_ * (eb), nO_ = v_ * (el), nX_ = x0_ * (eb);       \
    if ((tcur) < ilen) { aE = nE_; aO = nO_; aX = nX_; }            \
} while (0)

#define BSTEP(el, eb) do {                                          \
    float t1_ = (el) * bO;                                          \
    float t2_ = (eb) * bE;                                          \
    float d_  = fmaf(t1_, za, t2_);                                 \
    float pd_ = __shfl_down_sync(0xffffffffu, d_, 1);               \
    float xb_ = (eb) * bX;                                          \
    if (lane == 31) pd_ = xb_;                                      \
    bE = t2_ + t1_; bO = t1_ + pd_; bX = xb_;                       \
} while (0)

#define BSTEPP(el, eb, ecur) do {                                   \
    float t1_ = (el) * bO;                                          \
    float t2_ = (eb) * bE;                                          \
    float d_  = fmaf(t1_, za, t2_);                                 \
    float pd_ = __shfl_down_sync(0xffffffffu, d_, 1);               \
    float xb_ = (eb) * bX;                                          \
    if (lane == 31) pd_ = xb_;                                      \
    float nE_ = t2_ + t1_, nO_ = t1_ + pd_;                         \
    if ((ecur) < ilen) { bE = nE_; bO = nO_; bX = xb_; }            \
} while (0)

// Single-instruction warp max via REDUX (positive floats: bit order = value order)
#define RENORM(r0, r1, r2, SH) do {                                 \
    float ml_ = fmaxf(fmaxf(r0, r1), r2);                           \
    unsigned mu_ = __reduce_max_sync(0xffffffffu,                   \
                                     __float_as_uint(ml_));         \
    if (mu_) {                                                      \
        const int e_ = (int)((mu_ >> 23) & 255u) - 127;             \
        int sh_ = RN_TARGET - e_;                                   \
        if (sh_ > 127)  sh_ = 127;                                  \
        if (sh_ < -126) sh_ = -126;                                 \
        const float sc_ = __int_as_float((127 + sh_) << 23);        \
        r0 *= sc_; r1 *= sc_; r2 *= sc_;                            \
        SH += sh_;                                                  \
    }                                                               \
} while (0)

// ---------------------------------------------------------------------------
// Fused kernel. Grid (33, 32), 128 threads.
// Phase 1 (all blocks): gather one (batch, class) column, time-axis logsumexp,
//   write linear emissions to g_emit[b][s][:] (coalesced).
// Phase 2 (last block per batch only): meet-in-the-middle CTC recursion
//   (warp0 forward alpha t=0..255, warp1 backward beta t=511..256), combine
//   via dot product; last batch computes the mean. Counters reset for replay.
// ---------------------------------------------------------------------------
__global__ void ctc_fused_kernel(const float* __restrict__ lp,
                                 const int* __restrict__ targets,
                                 const int* __restrict__ ilens,
                                 const int* __restrict__ tlens,
                                 float* __restrict__ out) {
    const int s   = blockIdx.x;   // 0..32
    const int b   = blockIdx.y;
    const int tid = threadIdx.x;  // 0..127

    __shared__ float redm[4], reds[4];
    __shared__ float fA[SS], fB[SS];
    __shared__ int   sSH[2];
    __shared__ int   sOld;

    // ---------------- Phase 1: gather + lse + linearize --------------------
    {
        const int c = (s < 32) ? targets[b * LL + s] : BLANK_ID;
        const float* col = lp + (size_t)b * TT * CC + c;

        float v[4];
#pragma unroll
        for (int k = 0; k < 4; ++k)
            v[k] = __ldcs(col + (size_t)(tid + k * 128) * CC);

        float m = fmaxf(fmaxf(v[0], v[1]), fmaxf(v[2], v[3]));
#pragma unroll
        for (int o = 16; o; o >>= 1) m = fmaxf(m, __shfl_xor_sync(0xffffffffu, m, o));
        const int w = tid >> 5;
        if ((tid & 31) == 0) redm[w] = m;
        __syncthreads();
        m = fmaxf(fmaxf(redm[0], redm[1]), fmaxf(redm[2], redm[3]));

        float sum = 0.f;
#pragma unroll
        for (int k = 0; k < 4; ++k) sum += ex2f_((v[k] - m) * LOG2E);
#pragma unroll
        for (int o = 16; o; o >>= 1) sum += __shfl_xor_sync(0xffffffffu, sum, o);
        if ((tid & 31) == 0) reds[w] = sum;
        __syncthreads();
        sum = reds[0] + reds[1] + reds[2] + reds[3];

        const float lse2 = m * LOG2E + lg2f_(sum);

        float* dst = g_emit + ((size_t)b * NSC + s) * TT;
#pragma unroll
        for (int k = 0; k < 4; ++k)
            dst[tid + k * 128] = ex2f_(v[k] * LOG2E - lse2 + CSHIFT);
    }

    // make this block's emission writes device-visible, then count in
    __threadfence();
    __syncthreads();
    if (tid == 0) sOld = atomicAdd(&g_cnt[b], 1);
    __syncthreads();
    if (sOld != NSC - 1) return;     // not the last gather block for batch b

    // ---------------- Phase 2: recursion (winner block only) ---------------
    const int wid  = tid >> 5;
    const int lane = tid & 31;
    const float* em = g_emit + (size_t)b * NSC * TT;

    const int tgt = targets[b * LL + lane];
    const int tm1 = (lane > 0) ? targets[b * LL + lane - 1] : BLANK_ID;
    const float za = (lane > 0 && tgt != BLANK_ID && tgt != tm1) ? 1.f : 0.f;
    const float zb = (lane > 0) ? 1.f : 0.f;
    int ilen = ilens[b];
    if (ilen > TT) ilen = TT;

    const float* pL = em + (size_t)lane * TT;   // lane's label emissions
    const float* pB = em + (size_t)32  * TT;    // blank emissions (broadcast)

    if (wid == 0) {
        // ----- forward: alpha, t = 0 .. TH-1 -----
        float aE = (lane == 0) ? 1.f : 0.f;     // virtual alpha_{-1}
        float aO = 0.f, aX = 0.f;
        int SH = 0;

        float4 La = ldcg4_(pL + 0), Ba = ldcg4_(pB + 0);
        float4 Lb = ldcg4_(pL + 4), Bb = ldcg4_(pB + 4);

#pragma unroll 4
        for (int g = 0; g < 32; ++g) {
            const int t0 = 8 * g;
            // branchless prefetch: t0+8..t0+15 always within the 512-row
            const float4 nLa = ldcg4_(pL + t0 + 8);
            const float4 nBa = ldcg4_(pB + t0 + 8);
            const float4 nLb = ldcg4_(pL + t0 + 12);
            const float4 nBb = ldcg4_(pB + t0 + 12);

            if (t0 + 7 < ilen) {
                FSTEP(La.x, Ba.x); FSTEP(La.y, Ba.y);
                FSTEP(La.z, Ba.z); FSTEP(La.w, Ba.w);
                FSTEP(Lb.x, Bb.x); FSTEP(Lb.y, Bb.y);
                FSTEP(Lb.z, Bb.z); FSTEP(Lb.w, Bb.w);
            } else {
                FSTEPP(La.x, Ba.x, t0 + 0); FSTEPP(La.y, Ba.y, t0 + 1);
                FSTEPP(La.z, Ba.z, t0 + 2); FSTEPP(La.w, Ba.w, t0 + 3);
                FSTEPP(Lb.x, Bb.x, t0 + 4); FSTEPP(Lb.y, Bb.y, t0 + 5);
                FSTEPP(Lb.z, Bb.z, t0 + 6); FSTEPP(Lb.w, Bb.w, t0 + 7);
            }
            RENORM(aE, aO, aX, SH);
            La = nLa; Ba = nBa; Lb = nLb; Bb = nBb;
        }

        fA[2 * lane] = aE;
        fA[2 * lane + 1] = aO;
        if (lane == 31) fA[64] = aX;
        if (lane == 0)  sSH[0] = SH;
    } else if (wid == 1) {
        // ----- backward: beta, consuming emissions e = TT-1 down to TH -----
        const int tl = tlens[b];
        const int i1 = 2 * tl;
        const int i2 = (2 * tl - 1 > 0) ? (2 * tl - 1) : 0;
        float bE = ((2 * lane == i1) || (2 * lane == i2)) ? 1.f : 0.f;
        float bO = (2 * lane + 1 == i2) ? 1.f : 0.f;
        float bX = (i1 == 64) ? 1.f : 0.f;   // only lane 31's copy is used
        int SH = 0;

        float4 La = ldcg4_(pL + TT - 4), Ba = ldcg4_(pB + TT - 4);
        float4 Lb = ldcg4_(pL + TT - 8), Bb = ldcg4_(pB + TT - 8);

#pragma unroll 4
        for (int g = 0; g < 32; ++g) {
            const int ea = TT - 4 - 8 * g;   // group A covers e = ea+3..ea
            // branchless prefetch: ea-8 down to ea-12+3, min address pL+248
            const float4 nLa = ldcg4_(pL + ea - 8);
            const float4 nBa = ldcg4_(pB + ea - 8);
            const float4 nLb = ldcg4_(pL + ea - 12);
            const float4 nBb = ldcg4_(pB + ea - 12);

            if (ea + 3 < ilen) {
                BSTEP(La.w, Ba.w); BSTEP(La.z, Ba.z);
                BSTEP(La.y, Ba.y); BSTEP(La.x, Ba.x);
                BSTEP(Lb.w, Bb.w); BSTEP(Lb.z, Bb.z);
                BSTEP(Lb.y, Bb.y); BSTEP(Lb.x, Bb.x);
            } else {
                BSTEPP(La.w, Ba.w, ea + 3); BSTEPP(La.z, Ba.z, ea + 2);
                BSTEPP(La.y, Ba.y, ea + 1); BSTEPP(La.x, Ba.x, ea + 0);
                BSTEPP(Lb.w, Bb.w, ea - 1); BSTEPP(Lb.z, Bb.z, ea - 2);
                BSTEPP(Lb.y, Bb.y, ea - 3); BSTEPP(Lb.x, Bb.x, ea - 4);
            }
            RENORM(bE, bO, bX, SH);
            La = nLa; Ba = nBa; Lb = nLb; Bb = nBb;
        }

        fB[2 * lane] = bE;
        fB[2 * lane + 1] = bO;
        if (lane == 31) fB[64] = bX;
        if (lane == 0)  sSH[1] = SH;
    }

    __syncthreads();

    if (wid == 0) {
        // dot(alpha_{TH-1}, beta_{TH-1})
        float prod = fA[2 * lane] * fB[2 * lane]
                   + fA[2 * lane + 1] * fB[2 * lane + 1];
        if (lane == 31) prod = fmaf(fA[64], fB[64], prod);
#pragma unroll
        for (int o = 16; o; o >>= 1) prod += __shfl_xor_sync(0xffffffffu, prod, o);

        if (lane == 0) {
            const float tot = prod;
            float loss;
            if (tot > 0.f) {
                // stored = true * 2^(CSHIFT*ilen + SHa + SHb)
                const double ll2 = (double)lg2f_(tot)
                                 - (double)(sSH[0] + sSH[1])
                                 - (double)CSHIFT * (double)ilen;
                loss = (float)(-LN2d * ll2);
                if (!(loss < 1e20f)) loss = 0.f;   // zero_infinity
            } else {
                loss = 0.f;
            }
            const int tl = tlens[b];
            const int dn = (tl > 1) ? tl : 1;
            g_partial[b] = loss / (float)dn;
            g_cnt[b] = 0;                          // reset for next replay
            __threadfence();
        }
        __syncwarp();

        // deterministic last-batch mean (fixed-tree, counter reset)
        int old = 0;
        if (lane == 0) old = atomicAdd(&g_done, 1);
        old = __shfl_sync(0xffffffffu, old, 0);
        if (old == BB - 1) {
            float v = *((volatile float*)&g_partial[lane]);
#pragma unroll
            for (int o = 16; o; o >>= 1) v += __shfl_xor_sync(0xffffffffu, v, o);
            if (lane == 0) {
                out[0] = v * (1.0f / (float)BB);
                g_done = 0;                        // reset for next replay
            }
        }
    }
}

extern "C" void kernel_launch(void* const* d_in, const int* in_sizes, int n_in,
                              void* d_out, int out_size) {
    const float* lp      = (const float*)d_in[0];
    const int*   targets = (const int*)d_in[1];
    const int*   ilens   = (const int*)d_in[2];
    const int*   tlens   = (const int*)d_in[3];
    (void)in_sizes; (void)n_in; (void)out_size;

    ctc_fused_kernel<<<dim3(NSC, BB), 128>>>(lp, targets, ilens, tlens,
                                             (float*)d_out);
}